// round 1
// baseline (speedup 1.0000x reference)
#include <cuda_runtime.h>

// ---------------------------------------------------------------------------
// LBP histogram kernel, GB300 sm_103a
// img: [16,3,1024,1024] fp32  ->  out: [1,256] fp32 standardized histogram
// ---------------------------------------------------------------------------

#define IMG_H 1024
#define IMG_W 1024
#define IMG_B 16
#define HW (IMG_H * IMG_W)

#define THREADS 256
#define BLOCKS 444                     // 148 SMs * 3 blocks (64KB smem each)
#define WARPS_PER_BLOCK 8
#define TOTAL_WARPS (BLOCKS * WARPS_PER_BLOCK)   // 3552

#define CHUNK_ROWS 32
#define STRIPS_PER_IMG 32              // 1024 / 32 cols
#define CHUNKS_PER_STRIP (IMG_H / CHUNK_ROWS)    // 32
#define TOTAL_TASKS (IMG_B * STRIPS_PER_IMG * CHUNKS_PER_STRIP)  // 16384
// max tasks per warp = ceil(16384/3552) = 5 -> max 160 pixels/thread < 255 (u8 safe)

__device__ unsigned int g_count[256];

struct R3 { float l, c, r; };

__device__ __forceinline__ float gray3(const float* __restrict__ p) {
    // match XLA left-to-right reduction: ((0.299*r + 0.587*g) + 0.114*b)
    return fmaf(0.114f, p[2 * HW], fmaf(0.587f, p[HW], 0.299f * p[0]));
}

// Load one gray row for this warp's 32-column strip, with halo columns and
// zero padding for out-of-range rows. Returns (left, center, right) per lane.
__device__ __forceinline__ R3 load_row(const float* __restrict__ base, int r,
                                       int c0, int lane) {
    float g = 0.0f, hl = 0.0f, hr = 0.0f;
    if ((unsigned)r < (unsigned)IMG_H) {
        const float* p = base + (size_t)r * IMG_W;
        g = gray3(p + c0 + lane);
        if (lane == 0 && c0 > 0)              hl = gray3(p + c0 - 1);
        if (lane == 31 && c0 + 32 < IMG_W)    hr = gray3(p + c0 + 32);
    }
    float sl = __shfl_up_sync(0xffffffffu, g, 1);
    float sr = __shfl_down_sync(0xffffffffu, g, 1);
    R3 o;
    o.c = g;
    o.l = (lane == 0) ? hl : sl;
    o.r = (lane == 31) ? hr : sr;
    return o;
}

extern "C" __global__ void __launch_bounds__(THREADS)
lbp_main(const float* __restrict__ img) {
    extern __shared__ unsigned char hist[];   // 64 KB: hist[code*256 + tid]
    const int tid = threadIdx.x;

    // zero private histograms
    uint4* h4 = (uint4*)hist;
#pragma unroll
    for (int i = 0; i < 16; i++)
        h4[tid + i * THREADS] = make_uint4(0u, 0u, 0u, 0u);
    __syncthreads();

    const int lane = tid & 31;
    const int warp = tid >> 5;
    const int gw = blockIdx.x * WARPS_PER_BLOCK + warp;   // 0..3551

    for (int t = gw; t < TOTAL_TASKS; t += TOTAL_WARPS) {
        const int strip = t >> 5;          // 0..511
        const int chunk = t & 31;          // 0..31
        const int b = strip >> 5;          // image
        const int s = strip & 31;          // column strip within image
        const int c0 = s << 5;
        const int r0 = chunk << 5;
        const float* base = img + (size_t)b * 3 * HW;

        // prime 4-row sliding window (2-row load lookahead)
        R3 top = load_row(base, r0 - 1, c0, lane);
        R3 mid = load_row(base, r0,     c0, lane);
        R3 bot = load_row(base, r0 + 1, c0, lane);
        R3 nx  = load_row(base, r0 + 2, c0, lane);

#pragma unroll 4
        for (int r = r0; r < r0 + CHUNK_ROWS; r++) {
            R3 nx2 = load_row(base, r + 3, c0, lane);

            const float ctr = mid.c;
            unsigned code;
            code  = (top.r >= ctr) ?   1u : 0u;   // top-right
            code |= (mid.r >= ctr) ?   2u : 0u;   // right
            code |= (bot.r >= ctr) ?   4u : 0u;   // bottom-right
            code |= (bot.c >= ctr) ?   8u : 0u;   // bottom
            code |= (bot.l >= ctr) ?  16u : 0u;   // bottom-left
            code |= (mid.l >= ctr) ?  32u : 0u;   // left
            code |= (top.l >= ctr) ?  64u : 0u;   // top-left
            code |= (top.c >= ctr) ? 128u : 0u;   // top

            hist[(code << 8) + tid]++;            // thread-exclusive byte

            top = mid; mid = bot; bot = nx; nx = nx2;
        }
    }
    __syncthreads();

    // Block reduction: thread `tid` sums bin `tid` over 256 byte counters.
    // Rotated start offset makes lanes hit distinct banks (conflict-free).
    const unsigned int* h32 = (const unsigned int*)hist;
    unsigned int sum = 0;
    const int wbase = tid << 6;   // 64 words per bin
#pragma unroll 8
    for (int j = 0; j < 64; j++) {
        unsigned int w = h32[wbase + ((tid + j) & 63)];
        sum = __dp4a(w, 0x01010101u, sum);
    }
    atomicAdd(&g_count[tid], sum);
}

extern "C" __global__ void __launch_bounds__(256)
lbp_finalize(float* __restrict__ out) {
    __shared__ float sh[256];
    const int tid = threadIdx.x;

    // read-and-zero so every graph replay starts from a clean counter array
    unsigned int cnt = atomicExch(&g_count[tid], 0u);
    float h = (float)cnt;

    sh[tid] = h;
    __syncthreads();
    for (int s = 128; s > 0; s >>= 1) {
        if (tid < s) sh[tid] += sh[tid + s];
        __syncthreads();
    }
    const float mean = sh[0] * (1.0f / 256.0f);
    __syncthreads();

    const float d = h - mean;
    sh[tid] = d * d;
    __syncthreads();
    for (int s = 128; s > 0; s >>= 1) {
        if (tid < s) sh[tid] += sh[tid + s];
        __syncthreads();
    }
    const float stdv = sqrtf(sh[0] * (1.0f / 255.0f));   // ddof = 1
    out[tid] = d / stdv;
}

extern "C" void kernel_launch(void* const* d_in, const int* in_sizes, int n_in,
                              void* d_out, int out_size) {
    (void)in_sizes; (void)n_in; (void)out_size;
    const float* img = (const float*)d_in[0];
    float* out = (float*)d_out;

    cudaFuncSetAttribute(lbp_main, cudaFuncAttributeMaxDynamicSharedMemorySize,
                         65536);
    lbp_main<<<BLOCKS, THREADS, 65536>>>(img);
    lbp_finalize<<<1, 256>>>(out);
}

// round 3
// speedup vs baseline: 2.6820x; 2.6820x over previous
#include <cuda_runtime.h>

// ---------------------------------------------------------------------------
// LBP histogram kernel, GB300 sm_103a — round 2
// img: [16,3,1024,1024] fp32  ->  out: [1,256] fp32 standardized histogram
// float4 lanes (128-col strips), conflict-swizzled per-thread byte histograms,
// dynamic warp ticketing.
// ---------------------------------------------------------------------------

#define IMG_H 1024
#define IMG_W 1024
#define HW (IMG_H * IMG_W)

#define THREADS 256
#define BLOCKS 444                 // 148 SMs * 3 blocks (64 KB smem each)
#define CHUNK 32                   // rows per task
#define N_TASKS (16 * 8 * 32)      // 16 imgs * 8 strips(128 col) * 32 chunks

__device__ unsigned int g_count[256];
__device__ unsigned int g_ticket;

struct Row { float4 g; float l, r; };

__device__ __forceinline__ float gray1(float r, float g, float b) {
    return fmaf(0.114f, b, fmaf(0.587f, g, 0.299f * r));
}

// Load one gray row (4 px/lane) for a 128-column strip, halo cols + zero pad.
__device__ __forceinline__ Row load_row4(const float* __restrict__ base,
                                         int r, int rmax, int c0, int lane) {
    Row o;
    o.g = make_float4(0.f, 0.f, 0.f, 0.f);
    float hl = 0.f, hr = 0.f;
    if ((unsigned)r < (unsigned)IMG_H && r <= rmax) {
        const float* q = base + (size_t)r * IMG_W;
        const float* p = q + c0 + (lane << 2);
        float4 cr = *(const float4*)(p);
        float4 cg = *(const float4*)(p + HW);
        float4 cb = *(const float4*)(p + 2 * HW);
        o.g.x = gray1(cr.x, cg.x, cb.x);
        o.g.y = gray1(cr.y, cg.y, cb.y);
        o.g.z = gray1(cr.z, cg.z, cb.z);
        o.g.w = gray1(cr.w, cg.w, cb.w);
        if (lane == 0 && c0 > 0)
            hl = gray1(q[c0 - 1], q[c0 - 1 + HW], q[c0 - 1 + 2 * HW]);
        if (lane == 31 && c0 + 128 < IMG_W)
            hr = gray1(q[c0 + 128], q[c0 + 128 + HW], q[c0 + 128 + 2 * HW]);
    }
    float sl = __shfl_up_sync(0xffffffffu, o.g.w, 1);
    float sr = __shfl_down_sync(0xffffffffu, o.g.x, 1);
    o.l = (lane == 0) ? hl : sl;
    o.r = (lane == 31) ? hr : sr;
    return o;
}

__device__ __forceinline__ void upd(unsigned char* __restrict__ hist, int tid,
                                    float c, float tl, float t, float tr,
                                    float l, float rr, float bl, float b,
                                    float br) {
    unsigned code;
    code  = (tr >= c) ?   1u : 0u;   // top-right
    code |= (rr >= c) ?   2u : 0u;   // right
    code |= (br >= c) ?   4u : 0u;   // bottom-right
    code |= (b  >= c) ?   8u : 0u;   // bottom
    code |= (bl >= c) ?  16u : 0u;   // bottom-left
    code |= (l  >= c) ?  32u : 0u;   // left
    code |= (tl >= c) ?  64u : 0u;   // top-left
    code |= (t  >= c) ? 128u : 0u;   // top
    // swizzle: equal codes in a lane-quad -> same word (merge); different
    // codes -> different banks. Bytes remain thread-exclusive per code block.
    hist[(code << 8) + ((tid + (code << 2)) & 255)]++;
}

extern "C" __global__ void __launch_bounds__(THREADS, 3)
lbp_main(const float* __restrict__ img) {
    extern __shared__ unsigned char hist[];   // 64 KB
    const int tid = threadIdx.x;
    const int lane = tid & 31;

    uint4* h4 = (uint4*)hist;
#pragma unroll
    for (int i = 0; i < 16; i++)
        h4[tid + i * THREADS] = make_uint4(0u, 0u, 0u, 0u);
    __syncthreads();

    for (;;) {
        unsigned t;
        if (lane == 0) t = atomicAdd(&g_ticket, 1u);
        t = __shfl_sync(0xffffffffu, t, 0);
        if (t >= N_TASKS) break;

        const int chunk = t & 31;            // row chunk
        const int strip = (t >> 5) & 7;      // 128-col strip
        const int b = t >> 8;                // image
        const int c0 = strip << 7;
        const int r0 = chunk * CHUNK;
        const int rmax = r0 + CHUNK;         // deepest row actually needed
        const float* base = img + (size_t)b * 3 * HW;

        Row top = load_row4(base, r0 - 1, rmax, c0, lane);
        Row mid = load_row4(base, r0,     rmax, c0, lane);
        Row bot = load_row4(base, r0 + 1, rmax, c0, lane);
        Row nx  = load_row4(base, r0 + 2, rmax, c0, lane);

#pragma unroll 4
        for (int r = r0; r < r0 + CHUNK; r++) {
            Row nx2 = load_row4(base, r + 3, rmax, c0, lane);

            upd(hist, tid, mid.g.x, top.l,   top.g.x, top.g.y,
                mid.l,   mid.g.y, bot.l,   bot.g.x, bot.g.y);
            upd(hist, tid, mid.g.y, top.g.x, top.g.y, top.g.z,
                mid.g.x, mid.g.z, bot.g.x, bot.g.y, bot.g.z);
            upd(hist, tid, mid.g.z, top.g.y, top.g.z, top.g.w,
                mid.g.y, mid.g.w, bot.g.y, bot.g.z, bot.g.w);
            upd(hist, tid, mid.g.w, top.g.z, top.g.w, top.r,
                mid.g.z, mid.r,   bot.g.z, bot.g.w, bot.r);

            top = mid; mid = bot; bot = nx; nx = nx2;
        }
    }
    __syncthreads();

    // Block reduction: thread tid sums code block tid (64 words, rotated
    // start -> conflict-free). Swizzle is a per-code bijection, so the
    // block sum is unchanged.
    const unsigned int* h32 = (const unsigned int*)hist;
    unsigned int sum = 0;
    const int wbase = tid << 6;
#pragma unroll 8
    for (int j = 0; j < 64; j++) {
        unsigned int w = h32[wbase + ((tid + j) & 63)];
        sum = __dp4a(w, 0x01010101u, sum);
    }
    atomicAdd(&g_count[tid], sum);
}

extern "C" __global__ void __launch_bounds__(256)
lbp_finalize(float* __restrict__ out) {
    __shared__ float sh[256];
    const int tid = threadIdx.x;

    if (tid == 0) g_ticket = 0u;              // reset work queue for replay
    unsigned int cnt = atomicExch(&g_count[tid], 0u);
    float h = (float)cnt;

    sh[tid] = h;
    __syncthreads();
    for (int s = 128; s > 0; s >>= 1) {
        if (tid < s) sh[tid] += sh[tid + s];
        __syncthreads();
    }
    const float mean = sh[0] * (1.0f / 256.0f);
    __syncthreads();

    const float d = h - mean;
    sh[tid] = d * d;
    __syncthreads();
    for (int s = 128; s > 0; s >>= 1) {
        if (tid < s) sh[tid] += sh[tid + s];
        __syncthreads();
    }
    const float stdv = sqrtf(sh[0] * (1.0f / 255.0f));   // ddof = 1
    out[tid] = d / stdv;
}

extern "C" void kernel_launch(void* const* d_in, const int* in_sizes, int n_in,
                              void* d_out, int out_size) {
    (void)in_sizes; (void)n_in; (void)out_size;
    const float* img = (const float*)d_in[0];
    float* out = (float*)d_out;

    cudaFuncSetAttribute(lbp_main, cudaFuncAttributeMaxDynamicSharedMemorySize,
                         65536);
    lbp_main<<<BLOCKS, THREADS, 65536>>>(img);
    lbp_finalize<<<1, 256>>>(out);
}